// round 4
// baseline (speedup 1.0000x reference)
#include <cuda_runtime.h>
#include <math.h>

// Problem constants (fixed by the reference setup)
#define SS        7          // output bins per dim
#define NPROP     32
#define NCH       128
#define FD        32         // D/SCALE
#define FH        64         // H/SCALE
#define FW        64         // W/SCALE
#define LMAX      18         // max crop extent per dim: 64/4 + 2
#define THREADS   256
#define NWARP     (THREADS / 32)

__global__ __launch_bounds__(THREADS)
void crop_roi_kernel(const float* __restrict__ f,
                     const float* __restrict__ proposals,
                     float* __restrict__ out)
{
    // x-pooled crop: layout [z][y][bx] -> (z*Ly + y)*7 + bx
    __shared__ float crop7[LMAX * LMAX * SS];   // 9072 B

    const int n    = blockIdx.x;
    const int c    = blockIdx.y;
    const int tid  = threadIdx.x;
    const int lane = tid & 31;
    const int wid  = tid >> 5;

    // Crop box (redundant per thread; broadcast constant loads, cheap).
    const float* p = proposals + n * 8;
    const int b = (int)p[0];

    int c0[3], L[3];
    const int dims[3] = {FD, FH, FW};
#pragma unroll
    for (int d = 0; d < 3; d++) {
        const float ctr = p[2 + d];
        const float sd  = p[5 + d];
        int lo = (int)floorf((ctr - 0.5f * sd) * 0.25f);
        int hi = (int)ceilf ((ctr + 0.5f * sd) * 0.25f);
        lo = max(lo, 0);
        hi = min(hi, dims[d]);
        c0[d] = lo;
        L[d]  = hi - lo;     // >= 4 (side >= 16)
    }
    const int Lz = L[0], Ly = L[1], Lx = L[2];
    const int nrows = Lz * Ly;

    const float* fb = f + ((size_t)b * NCH + c) * (size_t)(FD * FH * FW);
    const int base = (c0[0] * FH + c0[1]) * FW + c0[2];

    // Per-lane x-window bounds (meaningful for lane < 7; window size <= 4).
    const int x0 =  lane      * Lx / SS;
    const int x1 = ((lane + 1) * Lx + SS - 1) / SS;

    // (z,y) for row r = wid, maintained incrementally (no runtime division).
    int z = 0, y = wid;
    while (y >= Ly) { y -= Ly; z++; }

    // Warp-per-row staging with fused x pooling.
    for (int r = wid; r < nrows; r += NWARP) {
        const float v = (lane < Lx)
            ? __ldg(&fb[base + (z * FH + y) * FW + lane])
            : -INFINITY;

        float m = -INFINITY;
#pragma unroll
        for (int k = 0; k < 4; k++) {
            const float t = __shfl_sync(0xffffffffu, v, (x0 + k) & 31);
            if (x0 + k < x1) m = fmaxf(m, t);
        }
        if (lane < SS) crop7[r * SS + lane] = m;

        y += NWARP;
        while (y >= Ly) { y -= Ly; z++; }
    }
    __syncthreads();

    // Pool (z,y): each bin reads <= 4*4 smem values.
    float* outp = out + ((size_t)n * NCH + c) * (SS * SS * SS);
    for (int bin = tid; bin < SS * SS * SS; bin += THREADS) {
        const int obx = bin % SS;          // const divisor -> magic multiply
        const int t1  = bin / SS;
        const int oby = t1 % SS;
        const int obz = t1 / SS;

        const int y0 =  oby      * Ly / SS;
        const int y1 = ((oby + 1) * Ly + SS - 1) / SS;
        const int z0 =  obz      * Lz / SS;
        const int z1 = ((obz + 1) * Lz + SS - 1) / SS;

        float m = -INFINITY;
        for (int zz = z0; zz < z1; zz++) {
            const float* row = &crop7[(zz * Ly + y0) * SS + obx];
            for (int yy = y0; yy < y1; yy++) {
                m = fmaxf(m, *row);
                row += SS;
            }
        }
        outp[bin] = m;
    }
}

extern "C" void kernel_launch(void* const* d_in, const int* in_sizes, int n_in,
                              void* d_out, int out_size)
{
    const float* f         = (const float*)d_in[0];
    // d_in[1] = inputs, only used for shape in the reference (static here)
    const float* proposals = (const float*)d_in[2];
    float* out = (float*)d_out;

    dim3 grid(NPROP, NCH);
    crop_roi_kernel<<<grid, THREADS>>>(f, proposals, out);
}

// round 6
// speedup vs baseline: 1.6543x; 1.6543x over previous
#include <cuda_runtime.h>
#include <math.h>

#define SS        7
#define NPROP     32
#define NCH       128
#define FD        32
#define FH        64
#define FW        64
#define LMAX      18         // max crop extent per dim
#define NROWMAX   (LMAX * LMAX)   // 324
#define THREADS   384

__global__ __launch_bounds__(THREADS)
void crop_roi_kernel(const float* __restrict__ f,
                     const float* __restrict__ proposals,
                     float* __restrict__ out)
{
    __shared__ int   rowoff[NROWMAX];                 // 1296 B
    __shared__ float crop7[NROWMAX * SS];             // x-pooled: [r][bx], 9072 B
    __shared__ float tmpzy[LMAX * SS * SS];           // y-pooled: [z][by][bx], 3528 B

    const int n   = blockIdx.x;
    const int c   = blockIdx.y;
    const int tid = threadIdx.x;

    // ---- Phase 0: box geometry (redundant per thread) + rowoff table ----
    const float* p = proposals + n * 8;
    const int b = (int)p[0];

    int c0[3], L[3];
    const int dims[3] = {FD, FH, FW};
#pragma unroll
    for (int d = 0; d < 3; d++) {
        const float ctr = p[2 + d];
        const float sd  = p[5 + d];
        int lo = (int)floorf((ctr - 0.5f * sd) * 0.25f);
        int hi = (int)ceilf ((ctr + 0.5f * sd) * 0.25f);
        lo = max(lo, 0);
        hi = min(hi, dims[d]);
        c0[d] = lo;
        L[d]  = hi - lo;     // >= 4 (side >= 16)
    }
    const int Lz = L[0], Ly = L[1], Lx = L[2];
    const int nrows = Lz * Ly;           // <= 324 < THREADS

    if (tid < nrows) {
        const int z = tid / Ly;          // one runtime div per thread, once
        const int y = tid - z * Ly;
        rowoff[tid] = ((c0[0] + z) * FH + (c0[1] + y)) * FW + c0[2];
    }

    const float* fb = f + ((size_t)b * NCH + c) * (size_t)(FD * FH * FW);
    __syncthreads();

    // ---- Phase 1: x-pool straight from gmem into crop7[r*7 + bx] ----
    const int ntask1 = nrows * SS;       // <= 2268
    for (int t = tid; t < ntask1; t += THREADS) {
        const int r  = t / SS;           // const divisor -> magic mult
        const int bx = t - r * SS;
        const int x0 =  bx      * Lx / SS;
        const int x1 = ((bx + 1) * Lx + SS - 1) / SS;   // x1 - x0 <= 4

        const float* rp = fb + rowoff[r] + x0;
        float m = __ldg(&rp[0]);                         // window nonempty
#pragma unroll
        for (int k = 1; k < 4; k++) {
            if (x0 + k < x1) m = fmaxf(m, __ldg(&rp[k]));
        }
        crop7[t] = m;
    }
    __syncthreads();

    // ---- Phase 2: y-pool crop7 -> tmpzy[z*49 + by*7 + bx] ----
    const int ntask2 = Lz * SS * SS;     // <= 882
    for (int t = tid; t < ntask2; t += THREADS) {
        const int zz  = t / (SS * SS);
        const int rem = t - zz * (SS * SS);
        const int by  = rem / SS;
        const int bx  = rem - by * SS;
        const int y0  =  by      * Ly / SS;
        const int y1  = ((by + 1) * Ly + SS - 1) / SS;   // <= 4 wide

        const float* rp = &crop7[(zz * Ly + y0) * SS + bx];
        float m = rp[0];
#pragma unroll
        for (int k = 1; k < 4; k++) {
            if (y0 + k < y1) m = fmaxf(m, rp[k * SS]);
        }
        tmpzy[t] = m;
    }
    __syncthreads();

    // ---- Phase 3: z-pool tmpzy -> out (343 bins, single pass) ----
    float* outp = out + ((size_t)n * NCH + c) * (SS * SS * SS);
    if (tid < SS * SS * SS) {
        const int bz   = tid / (SS * SS);
        const int rem  = tid - bz * (SS * SS);           // by*7+bx
        const int z0   =  bz      * Lz / SS;
        const int z1   = ((bz + 1) * Lz + SS - 1) / SS;  // <= 4 wide

        const float* rp = &tmpzy[z0 * (SS * SS) + rem];
        float m = rp[0];
#pragma unroll
        for (int k = 1; k < 4; k++) {
            if (z0 + k < z1) m = fmaxf(m, rp[k * SS * SS]);
        }
        outp[tid] = m;
    }
}

extern "C" void kernel_launch(void* const* d_in, const int* in_sizes, int n_in,
                              void* d_out, int out_size)
{
    const float* f         = (const float*)d_in[0];
    const float* proposals = (const float*)d_in[2];
    float* out = (float*)d_out;

    dim3 grid(NPROP, NCH);
    crop_roi_kernel<<<grid, THREADS>>>(f, proposals, out);
}

// round 7
// speedup vs baseline: 1.7816x; 1.0769x over previous
#include <cuda_runtime.h>
#include <math.h>

#define SS        7
#define NPROP     32
#define NCH       128
#define FD        32
#define FH        64
#define FW        64
#define LMAX      18              // max crop extent per dim
#define NROWMAX   (LMAX * LMAX)   // 324
#define THREADS   384
#define RSTRIDE   54              // floor(384/7) row-slots in phase 1
#define ZSTRIDE   7               // floor(343/49) z-slots in phase 2

__global__ __launch_bounds__(THREADS)
void crop_roi_kernel(const float* __restrict__ f,
                     const float* __restrict__ proposals,
                     float* __restrict__ out)
{
    __shared__ int   rowoff[NROWMAX];          // 1296 B
    __shared__ float crop7[NROWMAX * SS];      // x-pooled: [r][bx]   9072 B
    __shared__ float tmpzy[LMAX * SS * SS];    // y-pooled: [z][by][bx] 3528 B

    const int n   = blockIdx.x;
    const int c   = blockIdx.y;
    const int tid = threadIdx.x;

    // ---- Phase 0: box geometry (redundant per thread) + rowoff table ----
    const float* p = proposals + n * 8;
    const int b = (int)p[0];

    int c0[3], L[3];
    const int dims[3] = {FD, FH, FW};
#pragma unroll
    for (int d = 0; d < 3; d++) {
        const float ctr = p[2 + d];
        const float sd  = p[5 + d];
        int lo = (int)floorf((ctr - 0.5f * sd) * 0.25f);
        int hi = (int)ceilf ((ctr + 0.5f * sd) * 0.25f);
        lo = max(lo, 0);
        hi = min(hi, dims[d]);
        c0[d] = lo;
        L[d]  = hi - lo;     // >= 4 (side >= 16)
    }
    const int Lz = L[0], Ly = L[1], Lx = L[2];
    const int nrows = Lz * Ly;                 // <= 324 < THREADS

    if (tid < nrows) {
        const int z = tid / Ly;                // one runtime div, once
        const int y = tid - z * Ly;
        rowoff[tid] = ((c0[0] + z) * FH + (c0[1] + y)) * FW + c0[2];
    }

    const float* fb = f + ((size_t)b * NCH + c) * (size_t)(FD * FH * FW);
    __syncthreads();

    // ---- Phase 1: x-pool gmem -> crop7[r*7 + bx] ----
    // Thread layout: tid = r0*7 + bx  (bx, x-window constant per thread).
    {
        const int bx = tid % SS;               // const-divisor magic
        const int r0 = tid / SS;               // 0..54
        const int x0 =  bx      * Lx / SS;
        const int x1 = ((bx + 1) * Lx + SS - 1) / SS;
        const int w  = x1 - x0;                // 1..4, per-thread constant

        if (r0 < RSTRIDE) {
            for (int r = r0; r < nrows; r += RSTRIDE) {
                const float* rp = fb + rowoff[r] + x0;
                float m = __ldg(rp);
                if (w > 1) m = fmaxf(m, __ldg(rp + 1));
                if (w > 2) m = fmaxf(m, __ldg(rp + 2));
                if (w > 3) m = fmaxf(m, __ldg(rp + 3));
                crop7[r * SS + bx] = m;
            }
        }
    }
    __syncthreads();

    // ---- Phase 2: y-pool crop7 -> tmpzy[z*49 + by*7 + bx] ----
    // Thread layout: tid = zs*49 + rem  (y-window constant per thread).
    {
        const int zs  = tid / (SS * SS);       // 0..7
        const int rem = tid - zs * (SS * SS);  // by*7+bx
        const int by  = rem / SS;
        const int bx  = rem - by * SS;
        const int y0  =  by      * Ly / SS;
        const int y1  = ((by + 1) * Ly + SS - 1) / SS;
        const int wy  = y1 - y0;               // 1..4, per-thread constant

        if (zs < ZSTRIDE) {
            for (int zz = zs; zz < Lz; zz += ZSTRIDE) {
                const float* rp = &crop7[(zz * Ly + y0) * SS + bx];
                float m = rp[0];
                if (wy > 1) m = fmaxf(m, rp[SS]);
                if (wy > 2) m = fmaxf(m, rp[2 * SS]);
                if (wy > 3) m = fmaxf(m, rp[3 * SS]);
                tmpzy[zz * (SS * SS) + rem] = m;
            }
        }
    }
    __syncthreads();

    // ---- Phase 3: z-pool tmpzy -> out (343 bins, single shot) ----
    float* outp = out + ((size_t)n * NCH + c) * (SS * SS * SS);
    if (tid < SS * SS * SS) {
        const int bz  = tid / (SS * SS);
        const int rem = tid - bz * (SS * SS);
        const int z0  =  bz      * Lz / SS;
        const int z1  = ((bz + 1) * Lz + SS - 1) / SS;
        const int wz  = z1 - z0;               // 1..4

        const float* rp = &tmpzy[z0 * (SS * SS) + rem];
        float m = rp[0];
        if (wz > 1) m = fmaxf(m, rp[SS * SS]);
        if (wz > 2) m = fmaxf(m, rp[2 * SS * SS]);
        if (wz > 3) m = fmaxf(m, rp[3 * SS * SS]);
        outp[tid] = m;
    }
}

extern "C" void kernel_launch(void* const* d_in, const int* in_sizes, int n_in,
                              void* d_out, int out_size)
{
    const float* f         = (const float*)d_in[0];
    const float* proposals = (const float*)d_in[2];
    float* out = (float*)d_out;

    dim3 grid(NPROP, NCH);
    crop_roi_kernel<<<grid, THREADS>>>(f, proposals, out);
}

// round 8
// speedup vs baseline: 1.9563x; 1.0980x over previous
#include <cuda_runtime.h>
#include <math.h>

#define SS        7
#define NPROP     32
#define NCH       128
#define CPB       2               // channels per block
#define FD        32
#define FH        64
#define FW        64
#define CHVOL     (FD * FH * FW)
#define LMAX      18              // max crop extent per dim
#define NROWMAX   (LMAX * LMAX)   // 324
#define THREADS   384
#define RSTRIDE   54              // floor(384/7) row-slots in phase 1

__global__ __launch_bounds__(THREADS)
void crop_roi_kernel(const float* __restrict__ f,
                     const float* __restrict__ proposals,
                     float* __restrict__ out)
{
    __shared__ int   rowoff[NROWMAX];                   // 1296 B (shared by both channels)
    __shared__ float crop7[CPB][NROWMAX * SS];          // x-pooled              18144 B
    __shared__ float tmpzy[CPB][LMAX * SS * SS];        // y-pooled               7056 B

    const int n   = blockIdx.x;
    const int cg  = blockIdx.y;                         // channel group: c = cg*CPB + {0,1}
    const int tid = threadIdx.x;

    // ---- Phase 0: box geometry (redundant per thread) + rowoff table ----
    const float* p = proposals + n * 8;
    const int b = (int)p[0];

    int c0[3], L[3];
    const int dims[3] = {FD, FH, FW};
#pragma unroll
    for (int d = 0; d < 3; d++) {
        const float ctr = p[2 + d];
        const float sd  = p[5 + d];
        int lo = (int)floorf((ctr - 0.5f * sd) * 0.25f);
        int hi = (int)ceilf ((ctr + 0.5f * sd) * 0.25f);
        lo = max(lo, 0);
        hi = min(hi, dims[d]);
        c0[d] = lo;
        L[d]  = hi - lo;     // >= 4 (side >= 16)
    }
    const int Lz = L[0], Ly = L[1], Lx = L[2];
    const int nrows = Lz * Ly;                          // <= 324 < THREADS

    if (tid < nrows) {
        const int z = tid / Ly;                         // one runtime div, once
        const int y = tid - z * Ly;
        rowoff[tid] = ((c0[0] + z) * FH + (c0[1] + y)) * FW + c0[2];
    }

    const float* fb0 = f + ((size_t)b * NCH + cg * CPB) * (size_t)CHVOL;
    __syncthreads();

    // ---- Phase 1: x-pool gmem -> crop7[ch][r*7 + bx], both channels ----
    // Thread layout: tid = r0*7 + bx (x-window constant per thread).
    {
        const int bx = tid % SS;
        const int r0 = tid / SS;                        // 0..54
        const int x0 =  bx      * Lx / SS;
        const int x1 = ((bx + 1) * Lx + SS - 1) / SS;
        const int w  = x1 - x0;                         // 1..4, per-thread constant

        if (r0 < RSTRIDE) {
            for (int r = r0; r < nrows; r += RSTRIDE) {
                const float* rp0 = fb0 + rowoff[r] + x0;
                const float* rp1 = rp0 + CHVOL;
                // 8 independent loads in flight per iteration
                float m0 = __ldg(rp0);
                float m1 = __ldg(rp1);
                if (w > 1) { m0 = fmaxf(m0, __ldg(rp0 + 1)); m1 = fmaxf(m1, __ldg(rp1 + 1)); }
                if (w > 2) { m0 = fmaxf(m0, __ldg(rp0 + 2)); m1 = fmaxf(m1, __ldg(rp1 + 2)); }
                if (w > 3) { m0 = fmaxf(m0, __ldg(rp0 + 3)); m1 = fmaxf(m1, __ldg(rp1 + 3)); }
                crop7[0][r * SS + bx] = m0;
                crop7[1][r * SS + bx] = m1;
            }
        }
    }
    __syncthreads();

    // ---- Phase 2: y-pool crop7 -> tmpzy[ch][z*49 + by*7 + bx] ----
    // Task space: CPB * Lz * 49; thread layout keeps (by,bx) constant per thread.
    {
        const int rem = tid % (SS * SS);                // by*7+bx, per-thread constant
        const int s0  = tid / (SS * SS);                // 0..7  (z,ch slot)
        const int by  = rem / SS;
        const int bx  = rem - by * SS;
        const int y0  =  by      * Ly / SS;
        const int y1  = ((by + 1) * Ly + SS - 1) / SS;
        const int wy  = y1 - y0;                        // 1..4, per-thread constant

        const int ntask = CPB * Lz;                     // z-slots across channels
        for (int s = s0; s < ntask; s += THREADS / (SS * SS)) {
            const int ch = (s < Lz) ? 0 : 1;
            const int zz = (s < Lz) ? s : s - Lz;
            const float* rp = &crop7[ch][(zz * Ly + y0) * SS + bx];
            float m = rp[0];
            if (wy > 1) m = fmaxf(m, rp[SS]);
            if (wy > 2) m = fmaxf(m, rp[2 * SS]);
            if (wy > 3) m = fmaxf(m, rp[3 * SS]);
            tmpzy[ch][zz * (SS * SS) + rem] = m;
        }
    }
    __syncthreads();

    // ---- Phase 3: z-pool tmpzy -> out (CPB*343 bins over 384 threads) ----
    float* outp = out + ((size_t)n * NCH + cg * CPB) * (SS * SS * SS);
    {
        const int bz0  = tid / (SS * SS);               // 0..7
        const int rem  = tid - bz0 * (SS * SS);
        for (int s = bz0; s < CPB * SS; s += THREADS / (SS * SS)) {
            const int ch = (s < SS) ? 0 : 1;
            const int bz = (s < SS) ? s : s - SS;
            const int z0 =  bz      * Lz / SS;
            const int z1 = ((bz + 1) * Lz + SS - 1) / SS;
            const int wz = z1 - z0;                     // 1..4

            const float* rp = &tmpzy[ch][z0 * (SS * SS) + rem];
            float m = rp[0];
            if (wz > 1) m = fmaxf(m, rp[SS * SS]);
            if (wz > 2) m = fmaxf(m, rp[2 * SS * SS]);
            if (wz > 3) m = fmaxf(m, rp[3 * SS * SS]);
            outp[(size_t)ch * (SS * SS * SS) + bz * (SS * SS) + rem] = m;
        }
    }
}

extern "C" void kernel_launch(void* const* d_in, const int* in_sizes, int n_in,
                              void* d_out, int out_size)
{
    const float* f         = (const float*)d_in[0];
    const float* proposals = (const float*)d_in[2];
    float* out = (float*)d_out;

    dim3 grid(NPROP, NCH / CPB);
    crop_roi_kernel<<<grid, THREADS>>>(f, proposals, out);
}